// round 1
// baseline (speedup 1.0000x reference)
#include <cuda_runtime.h>
#include <cuda_bf16.h>
#include <cstdint>
#include <math.h>

#define N 8192
#define D 1024
#define BM 64
#define BN 128
#define BK 64
#define RSTR 72      // smem k-stride in bf16 elems (64 data + 8 pad -> conflict-free)
#define SSTR 132     // S tile row stride in floats (128 + 4 pad)
#define THREADS 256
#define STEPS (D / BK)   // 16
#define NJT (N / BN)     // 64

// 89600 bytes of dynamic smem for the main kernel
#define SMEM_BYTES (2*BM*RSTR*2 + 2*BN*RSTR*2 + BM*SSTR*4 + 2*BM*4)

// Device scratch (allocation-free rule: __device__ globals)
__device__ __nv_bfloat16 g_Rb[(long)N * D];
__device__ __nv_bfloat16 g_Lb[(long)N * D];
__device__ float g_lse[N];
__device__ float g_diag[N];

// ---------------------------------------------------------------------------
// Kernel 1: fp32 -> bf16 conversion of both inputs
// ---------------------------------------------------------------------------
__global__ void convert_kernel(const float* __restrict__ R, const float* __restrict__ L) {
    long i = ((long)blockIdx.x * blockDim.x + threadIdx.x) * 4;
    if (i >= (long)N * D) return;
    float4 r = *(const float4*)(R + i);
    float4 l = *(const float4*)(L + i);
    *(__nv_bfloat162*)(g_Rb + i)     = __floats2bfloat162_rn(r.x, r.y);
    *(__nv_bfloat162*)(g_Rb + i + 2) = __floats2bfloat162_rn(r.z, r.w);
    *(__nv_bfloat162*)(g_Lb + i)     = __floats2bfloat162_rn(l.x, l.y);
    *(__nv_bfloat162*)(g_Lb + i + 2) = __floats2bfloat162_rn(l.z, l.w);
}

// ---------------------------------------------------------------------------
// Kernel 2: exact fp32 diagonal dot products. One warp per row.
// ---------------------------------------------------------------------------
__global__ void diag_kernel(const float* __restrict__ R, const float* __restrict__ L) {
    int row  = blockIdx.x * 8 + (threadIdx.x >> 5);
    int lane = threadIdx.x & 31;
    const float* r = R + (long)row * D;
    const float* l = L + (long)row * D;
    float s = 0.f;
    #pragma unroll 8
    for (int k = lane; k < D; k += 32) s += r[k] * l[k];
    #pragma unroll
    for (int o = 16; o > 0; o >>= 1) s += __shfl_xor_sync(0xffffffffu, s, o);
    if (lane == 0) g_diag[row] = s;
}

// ---------------------------------------------------------------------------
// Kernel 3: fused GEMM + online logsumexp (flash-style)
// ---------------------------------------------------------------------------
__device__ __forceinline__ void cp16(void* s, const void* g) {
    unsigned ss = (unsigned)__cvta_generic_to_shared(s);
    asm volatile("cp.async.cg.shared.global [%0],[%1],16;\n" :: "r"(ss), "l"(g));
}

__global__ void __launch_bounds__(THREADS, 1) lse_kernel() {
    extern __shared__ char smem_raw[];
    __nv_bfloat16* Rt = (__nv_bfloat16*)smem_raw;           // 2 bufs of [BM][RSTR]
    __nv_bfloat16* Lt = Rt + 2 * BM * RSTR;                 // 2 bufs of [BN][RSTR]
    float* S    = (float*)(Lt + 2 * BN * RSTR);             // [BM][SSTR]
    float* smax = S + BM * SSTR;                            // [BM]
    float* ssum = smax + BM;                                // [BM]

    const int tid  = threadIdx.x;
    const int lane = tid & 31, warp = tid >> 5;
    const int wm = warp >> 2, wn = warp & 3;     // 2x4 warp grid of 32x32 tiles
    const int g  = lane >> 2, tg = lane & 3;
    const int rowBase = blockIdx.x * BM;

    if (tid < BM) { smax[tid] = -INFINITY; ssum[tid] = 0.f; }
    __syncthreads();

    for (int jt = 0; jt < NJT; ++jt) {
        const long colBase = (long)jt * BN;
        float c[2][4][4];
        #pragma unroll
        for (int mi = 0; mi < 2; mi++)
            #pragma unroll
            for (int ni = 0; ni < 4; ni++)
                #pragma unroll
                for (int q = 0; q < 4; q++) c[mi][ni][q] = 0.f;

        // prologue: stage chunk 0 into buffer 0
        {
            #pragma unroll
            for (int cc = 0; cc < (BM * BK / 8) / THREADS; ++cc) {   // 2
                int idx = cc * THREADS + tid;
                int row = idx >> 3, col = (idx & 7) * 8;
                cp16(Rt + row * RSTR + col, g_Rb + (long)(rowBase + row) * D + col);
            }
            #pragma unroll
            for (int cc = 0; cc < (BN * BK / 8) / THREADS; ++cc) {   // 4
                int idx = cc * THREADS + tid;
                int row = idx >> 3, col = (idx & 7) * 8;
                cp16(Lt + row * RSTR + col, g_Lb + (colBase + row) * D + col);
            }
            asm volatile("cp.async.commit_group;\n");
        }

        for (int kc = 0; kc < STEPS; ++kc) {
            if (kc + 1 < STEPS) {
                int kb = (kc + 1) * BK;
                int nbuf = (kc + 1) & 1;
                __nv_bfloat16* rb = Rt + nbuf * BM * RSTR;
                __nv_bfloat16* lb = Lt + nbuf * BN * RSTR;
                #pragma unroll
                for (int cc = 0; cc < (BM * BK / 8) / THREADS; ++cc) {
                    int idx = cc * THREADS + tid;
                    int row = idx >> 3, col = (idx & 7) * 8;
                    cp16(rb + row * RSTR + col, g_Rb + (long)(rowBase + row) * D + kb + col);
                }
                #pragma unroll
                for (int cc = 0; cc < (BN * BK / 8) / THREADS; ++cc) {
                    int idx = cc * THREADS + tid;
                    int row = idx >> 3, col = (idx & 7) * 8;
                    cp16(lb + row * RSTR + col, g_Lb + (colBase + row) * D + kb + col);
                }
            }
            asm volatile("cp.async.commit_group;\n");
            asm volatile("cp.async.wait_group 1;\n");
            __syncthreads();

            const __nv_bfloat16* rb = Rt + (kc & 1) * BM * RSTR + (wm * 32) * RSTR;
            const __nv_bfloat16* lb = Lt + (kc & 1) * BN * RSTR + (wn * 32) * RSTR;
            #pragma unroll
            for (int kk = 0; kk < BK / 16; ++kk) {
                const int k0 = kk * 16 + 2 * tg;
                uint32_t a[2][4];
                #pragma unroll
                for (int mi = 0; mi < 2; mi++) {
                    const __nv_bfloat16* base = rb + (mi * 16 + g) * RSTR;
                    a[mi][0] = *(const uint32_t*)(base + k0);
                    a[mi][1] = *(const uint32_t*)(base + 8 * RSTR + k0);
                    a[mi][2] = *(const uint32_t*)(base + k0 + 8);
                    a[mi][3] = *(const uint32_t*)(base + 8 * RSTR + k0 + 8);
                }
                #pragma unroll
                for (int ni = 0; ni < 4; ni++) {
                    const __nv_bfloat16* base = lb + (ni * 8 + g) * RSTR;
                    uint32_t b0 = *(const uint32_t*)(base + k0);
                    uint32_t b1 = *(const uint32_t*)(base + k0 + 8);
                    #pragma unroll
                    for (int mi = 0; mi < 2; mi++) {
                        asm volatile(
                            "mma.sync.aligned.m16n8k16.row.col.f32.bf16.bf16.f32 "
                            "{%0,%1,%2,%3},{%4,%5,%6,%7},{%8,%9},{%0,%1,%2,%3};"
                            : "+f"(c[mi][ni][0]), "+f"(c[mi][ni][1]),
                              "+f"(c[mi][ni][2]), "+f"(c[mi][ni][3])
                            : "r"(a[mi][0]), "r"(a[mi][1]), "r"(a[mi][2]), "r"(a[mi][3]),
                              "r"(b0), "r"(b1));
                    }
                }
            }
            __syncthreads();
        }

        // epilogue: S tile -> smem, then online LSE update
        #pragma unroll
        for (int mi = 0; mi < 2; mi++)
            #pragma unroll
            for (int ni = 0; ni < 4; ni++) {
                int row = wm * 32 + mi * 16 + g;
                int col = wn * 32 + ni * 8 + 2 * tg;
                *(float2*)&S[row * SSTR + col]       = make_float2(c[mi][ni][0], c[mi][ni][1]);
                *(float2*)&S[(row + 8) * SSTR + col] = make_float2(c[mi][ni][2], c[mi][ni][3]);
            }
        __syncthreads();
        {
            int row = tid >> 2, sub = tid & 3;     // 4 threads per row, stride-4 cols
            const float* srow = S + row * SSTR;
            float mx = -INFINITY;
            #pragma unroll
            for (int i = 0; i < BN / 4; i++) mx = fmaxf(mx, srow[sub + 4 * i]);
            mx = fmaxf(mx, __shfl_xor_sync(0xffffffffu, mx, 1));
            mx = fmaxf(mx, __shfl_xor_sync(0xffffffffu, mx, 2));
            float mold = smax[row];
            float nm = fmaxf(mold, mx);
            float sum = 0.f;
            #pragma unroll
            for (int i = 0; i < BN / 4; i++) sum += __expf(srow[sub + 4 * i] - nm);
            sum += __shfl_xor_sync(0xffffffffu, sum, 1);
            sum += __shfl_xor_sync(0xffffffffu, sum, 2);
            if (sub == 0) {
                float corr = (mold == -INFINITY) ? 0.f : __expf(mold - nm);
                ssum[row] = ssum[row] * corr + sum;
                smax[row] = nm;
            }
        }
        __syncthreads();
    }

    if (tid < BM) g_lse[rowBase + tid] = smax[tid] + logf(ssum[tid]);
}

// ---------------------------------------------------------------------------
// Kernel 4: final reduction (double accumulation for a clean scalar)
// ---------------------------------------------------------------------------
__global__ void finalize_kernel(float* __restrict__ out) {
    __shared__ double red[256];
    double acc = 0.0;
    for (int i = threadIdx.x; i < N; i += 256)
        acc += (double)g_lse[i] - (double)g_diag[i];
    red[threadIdx.x] = acc;
    __syncthreads();
    for (int s = 128; s > 0; s >>= 1) {
        if (threadIdx.x < s) red[threadIdx.x] += red[threadIdx.x + s];
        __syncthreads();
    }
    if (threadIdx.x == 0) out[0] = (float)(red[0] / (double)N);
}

// ---------------------------------------------------------------------------
extern "C" void kernel_launch(void* const* d_in, const int* in_sizes, int n_in,
                              void* d_out, int out_size) {
    const float* R = (const float*)d_in[0];   // rpr_r [N, D]
    const float* L = (const float*)d_in[1];   // rpr_l [N, D]
    float* out = (float*)d_out;

    cudaFuncSetAttribute(lse_kernel, cudaFuncAttributeMaxDynamicSharedMemorySize, SMEM_BYTES);

    convert_kernel<<<(int)(((long)N * D / 4) / 256), 256>>>(R, L);
    diag_kernel<<<N / 8, 256>>>(R, L);
    lse_kernel<<<N / BM, THREADS, SMEM_BYTES>>>();
    finalize_kernel<<<1, 256>>>(out);
}